// round 1
// baseline (speedup 1.0000x reference)
#include <cuda_runtime.h>
#include <cuda_bf16.h>
#include <math.h>

#define H      1024
#define T      4096
#define GATES  4096         // 4*H
#define NB0    64           // layer-0 blocks
#define NB1    64           // layer-1 blocks
#define NBLK   (NB0 + NB1)  // 128 total blocks (<= 148 SMs -> co-resident)
#define NTHR   512          // 16 warps -> 16 h-indices... no: 16 warps, 64 blocks * 16 = 1024 h-idx

// Persistent state (device globals; re-initialized each launch)
__device__ float    g_h0[2][H];
__device__ float    g_h1[2][H];
__device__ unsigned g_count;
__device__ unsigned g_gen;

__device__ __forceinline__ float sigmoidf_(float x) {
    return 1.0f / (1.0f + __expf(-x));
}

__device__ __forceinline__ void grid_sync() {
    __syncthreads();
    if (threadIdx.x == 0) {
        volatile unsigned* vgen = &g_gen;
        unsigned gen = *vgen;
        __threadfence();
        if (atomicAdd(&g_count, 1u) == NBLK - 1u) {
            g_count = 0u;
            __threadfence();
            *vgen = gen + 1u;
        } else {
            while (*vgen == gen) { /* spin */ }
        }
        __threadfence();
    }
    __syncthreads();
}

__global__ __launch_bounds__(NTHR, 1)
void lstm_persistent(const int* __restrict__ idx,
                     const float* __restrict__ emb,
                     const float* __restrict__ W_ih,
                     const float* __restrict__ W_hh,
                     const float* __restrict__ b_ih,
                     const float* __restrict__ b_hh,
                     float* __restrict__ out) {
    const int tid  = threadIdx.x;
    const int warp = tid >> 5;
    const int lane = tid & 31;
    const int blk  = blockIdx.x;
    const bool isL1 = (blk >= NB0);
    const int layer = isL1 ? 1 : 0;
    const int j = (isL1 ? (blk - NB0) : blk) * 16 + warp;   // h-index 0..1023

    const float* wih = W_ih + (size_t)layer * GATES * H;
    const float* whh = W_hh + (size_t)layer * GATES * H;

    float bias[4];
#pragma unroll
    for (int g = 0; g < 4; ++g)
        bias[g] = b_ih[layer * GATES + g * H + j] + b_hh[layer * GATES + g * H + j];

    float c = 0.0f;

    __shared__ float s_inp[H];
    __shared__ float s_h[H];

    // Re-zero hidden-state buffers every launch (block 0), then sync grid.
    if (blk == 0) {
        for (int i = tid; i < H; i += NTHR) {
            g_h0[0][i] = 0.0f; g_h0[1][i] = 0.0f;
            g_h1[0][i] = 0.0f; g_h1[1][i] = 0.0f;
        }
    }
    grid_sync();

    const size_t OUTS  = (size_t)T * H;      // outs [T,H]
    const size_t HT    = OUTS;               // hT [L,1,H]
    const size_t CT    = OUTS + 2 * H;       // cT [L,1,H]

    for (int p = 0; p <= T; ++p) {
        const bool active = isL1 ? (p >= 1) : (p < T);
        if (active) {
            const int t = isL1 ? (p - 1) : p;

            // Stage input vector and recurrent-h vector into SMEM.
            const float* inp_g = isL1 ? &g_h0[(p - 1) & 1][0]
                                      : emb + (size_t)__ldg(&idx[p]) * H;
            const float* hrec_g = isL1 ? &g_h1[p & 1][0]
                                       : &g_h0[(p - 1) & 1][0];
            for (int i = tid; i < H; i += NTHR) {
                s_inp[i] = inp_g[i];
                s_h[i]   = hrec_g[i];
            }
            __syncthreads();

            // 4 gate rows for this h-index: rows j, H+j, 2H+j, 3H+j.
            float acc[4];
#pragma unroll
            for (int g = 0; g < 4; ++g) {
                const float4* wr_i = (const float4*)(wih + (size_t)(g * H + j) * H);
                const float4* wr_h = (const float4*)(whh + (size_t)(g * H + j) * H);
                const float4* vi   = (const float4*)s_inp;
                const float4* vh   = (const float4*)s_h;
                float a = 0.0f;
#pragma unroll
                for (int it = 0; it < 8; ++it) {
                    const int k4 = lane + it * 32;
                    float4 w = wr_i[k4];
                    float4 v = vi[k4];
                    a = fmaf(w.x, v.x, a); a = fmaf(w.y, v.y, a);
                    a = fmaf(w.z, v.z, a); a = fmaf(w.w, v.w, a);
                    float4 w2 = wr_h[k4];
                    float4 v2 = vh[k4];
                    a = fmaf(w2.x, v2.x, a); a = fmaf(w2.y, v2.y, a);
                    a = fmaf(w2.z, v2.z, a); a = fmaf(w2.w, v2.w, a);
                }
                acc[g] = a;
            }
            // Butterfly reduce -> every lane holds all 4 sums.
#pragma unroll
            for (int off = 16; off > 0; off >>= 1) {
#pragma unroll
                for (int g = 0; g < 4; ++g)
                    acc[g] += __shfl_xor_sync(0xFFFFFFFFu, acc[g], off);
            }

            const float ig = sigmoidf_(acc[0] + bias[0]);
            const float fg = sigmoidf_(acc[1] + bias[1]);
            const float gg = tanhf(acc[2] + bias[2]);
            const float og = sigmoidf_(acc[3] + bias[3]);
            c = fg * c + ig * gg;
            const float h = og * tanhf(c);

            if (lane == 0) {
                if (isL1) {
                    g_h1[(p - 1) & 1][j] = h;
                    out[(size_t)t * H + j] = h;
                    if (t == T - 1) {
                        out[HT + H + j] = h;   // hT[1]
                        out[CT + H + j] = c;   // cT[1]
                    }
                } else {
                    g_h0[p & 1][j] = h;
                    if (p == T - 1) {
                        out[HT + j] = h;       // hT[0]
                        out[CT + j] = c;       // cT[0]
                    }
                }
            }
        }
        grid_sync();
    }
}

extern "C" void kernel_launch(void* const* d_in, const int* in_sizes, int n_in,
                              void* d_out, int out_size) {
    const int*   idx  = (const int*)d_in[0];
    const float* emb  = (const float*)d_in[1];
    const float* W_ih = (const float*)d_in[2];
    const float* W_hh = (const float*)d_in[3];
    const float* b_ih = (const float*)d_in[4];
    const float* b_hh = (const float*)d_in[5];
    float* out = (float*)d_out;

    lstm_persistent<<<NBLK, NTHR>>>(idx, emb, W_ih, W_hh, b_ih, b_hh, out);
    (void)in_sizes; (void)n_in; (void)out_size;
}

// round 6
// speedup vs baseline: 1.2222x; 1.2222x over previous
#include <cuda_runtime.h>
#include <cuda_fp16.h>
#include <math.h>

#define H      1024
#define T      4096
#define GATES  4096         // 4*H
#define NB0    64
#define NB1    64
#define NBLK   (NB0 + NB1)
#define NTHR   512

// fp16 copies of the weights (built by a prologue kernel each launch)
__device__ __align__(16) __half g_wih[2u * GATES * H];
__device__ __align__(16) __half g_whh[2u * GATES * H];

__device__ float    g_h0[2][H];
__device__ float    g_h1[2][H];
__device__ unsigned g_count;
__device__ unsigned g_gen;

__device__ __forceinline__ float sigmoidf_(float x) {
    return 1.0f / (1.0f + __expf(-x));
}

__device__ __forceinline__ void grid_sync() {
    __syncthreads();
    if (threadIdx.x == 0) {
        volatile unsigned* vgen = &g_gen;
        unsigned gen = *vgen;
        __threadfence();
        if (atomicAdd(&g_count, 1u) == NBLK - 1u) {
            g_count = 0u;
            __threadfence();
            *vgen = gen + 1u;
        } else {
            while (*vgen == gen) { /* spin */ }
        }
        __threadfence();
    }
    __syncthreads();
}

// fp32 -> fp16 weight conversion (runs every launch; ~0.2 GB traffic ≈ 25us)
__global__ void convert_weights(const float* __restrict__ W_ih,
                                const float* __restrict__ W_hh) {
    const unsigned n4 = 2u * GATES * H / 4u;   // float4 count per matrix
    for (unsigned i = blockIdx.x * blockDim.x + threadIdx.x; i < n4;
         i += gridDim.x * blockDim.x) {
        float4 a = ((const float4*)W_ih)[i];
        float4 b = ((const float4*)W_hh)[i];
        __half2* oi = (__half2*)g_wih;
        __half2* oh = (__half2*)g_whh;
        oi[2 * i + 0] = __floats2half2_rn(a.x, a.y);
        oi[2 * i + 1] = __floats2half2_rn(a.z, a.w);
        oh[2 * i + 0] = __floats2half2_rn(b.x, b.y);
        oh[2 * i + 1] = __floats2half2_rn(b.z, b.w);
    }
}

__global__ __launch_bounds__(NTHR, 1)
void lstm_persistent(const int* __restrict__ idx,
                     const float* __restrict__ emb,
                     const float* __restrict__ b_ih,
                     const float* __restrict__ b_hh,
                     float* __restrict__ out) {
    const int tid  = threadIdx.x;
    const int warp = tid >> 5;
    const int lane = tid & 31;
    const int blk  = blockIdx.x;
    const bool isL1 = (blk >= NB0);
    const int layer = isL1 ? 1 : 0;
    const int j = (isL1 ? (blk - NB0) : blk) * 16 + warp;   // h-index 0..1023

    const __half* wih = g_wih + (size_t)layer * GATES * H;
    const __half* whh = g_whh + (size_t)layer * GATES * H;

    float bias[4];
#pragma unroll
    for (int g = 0; g < 4; ++g)
        bias[g] = b_ih[layer * GATES + g * H + j] + b_hh[layer * GATES + g * H + j];

    float c = 0.0f;

    __shared__ float s_inp[H];
    __shared__ float s_h[H];

    if (blk == 0) {
        for (int i = tid; i < H; i += NTHR) {
            g_h0[0][i] = 0.0f; g_h0[1][i] = 0.0f;
            g_h1[0][i] = 0.0f; g_h1[1][i] = 0.0f;
        }
    }
    grid_sync();

    const size_t OUTS = (size_t)T * H;
    const size_t HT   = OUTS;
    const size_t CT   = OUTS + 2 * H;

    for (int p = 0; p <= T; ++p) {
        const bool active = isL1 ? (p >= 1) : (p < T);
        if (active) {
            const int t = isL1 ? (p - 1) : p;

            const float* inp_g  = isL1 ? &g_h0[(p - 1) & 1][0]
                                       : emb + (size_t)__ldg(&idx[p]) * H;
            const float* hrec_g = isL1 ? &g_h1[p & 1][0]
                                       : &g_h0[(p - 1) & 1][0];
            for (int i = tid; i < H; i += NTHR) {
                s_inp[i] = inp_g[i];
                s_h[i]   = hrec_g[i];
            }
            __syncthreads();

            float acc[4];
#pragma unroll
            for (int g = 0; g < 4; ++g) {
                // one gate row: H fp16 = 2048B = 128 uint4 (8 halves each)
                const uint4* wr_i = (const uint4*)(wih + (size_t)(g * H + j) * H);
                const uint4* wr_h = (const uint4*)(whh + (size_t)(g * H + j) * H);
                const float4* vi  = (const float4*)s_inp;
                const float4* vh  = (const float4*)s_h;
                float a = 0.0f;
#pragma unroll
                for (int it = 0; it < 4; ++it) {
                    const int k = lane + it * 32;       // uint4 index 0..127
                    uint4 wi = wr_i[k];
                    uint4 wh = wr_h[k];
                    float4 v0 = vi[2 * k + 0];
                    float4 v1 = vi[2 * k + 1];
                    float4 u0 = vh[2 * k + 0];
                    float4 u1 = vh[2 * k + 1];

                    float2 w0 = __half22float2(*(__half2*)&wi.x);
                    float2 w1 = __half22float2(*(__half2*)&wi.y);
                    float2 w2 = __half22float2(*(__half2*)&wi.z);
                    float2 w3 = __half22float2(*(__half2*)&wi.w);
                    a = fmaf(w0.x, v0.x, a); a = fmaf(w0.y, v0.y, a);
                    a = fmaf(w1.x, v0.z, a); a = fmaf(w1.y, v0.w, a);
                    a = fmaf(w2.x, v1.x, a); a = fmaf(w2.y, v1.y, a);
                    a = fmaf(w3.x, v1.z, a); a = fmaf(w3.y, v1.w, a);

                    float2 x0 = __half22float2(*(__half2*)&wh.x);
                    float2 x1 = __half22float2(*(__half2*)&wh.y);
                    float2 x2 = __half22float2(*(__half2*)&wh.z);
                    float2 x3 = __half22float2(*(__half2*)&wh.w);
                    a = fmaf(x0.x, u0.x, a); a = fmaf(x0.y, u0.y, a);
                    a = fmaf(x1.x, u0.z, a); a = fmaf(x1.y, u0.w, a);
                    a = fmaf(x2.x, u1.x, a); a = fmaf(x2.y, u1.y, a);
                    a = fmaf(x3.x, u1.z, a); a = fmaf(x3.y, u1.w, a);
                }
                acc[g] = a;
            }
#pragma unroll
            for (int off = 16; off > 0; off >>= 1) {
#pragma unroll
                for (int g = 0; g < 4; ++g)
                    acc[g] += __shfl_xor_sync(0xFFFFFFFFu, acc[g], off);
            }

            const float ig = sigmoidf_(acc[0] + bias[0]);
            const float fg = sigmoidf_(acc[1] + bias[1]);
            const float gg = tanhf(acc[2] + bias[2]);
            const float og = sigmoidf_(acc[3] + bias[3]);
            c = fg * c + ig * gg;
            const float h = og * tanhf(c);

            if (lane == 0) {
                if (isL1) {
                    g_h1[(p - 1) & 1][j] = h;
                    out[(size_t)t * H + j] = h;
                    if (t == T - 1) {
                        out[HT + H + j] = h;
                        out[CT + H + j] = c;
                    }
                } else {
                    g_h0[p & 1][j] = h;
                    if (p == T - 1) {
                        out[HT + j] = h;
                        out[CT + j] = c;
                    }
                }
            }
        }
        grid_sync();
    }
}

extern "C" void kernel_launch(void* const* d_in, const int* in_sizes, int n_in,
                              void* d_out, int out_size) {
    const int*   idx  = (const int*)d_in[0];
    const float* emb  = (const float*)d_in[1];
    const float* W_ih = (const float*)d_in[2];
    const float* W_hh = (const float*)d_in[3];
    const float* b_ih = (const float*)d_in[4];
    const float* b_hh = (const float*)d_in[5];
    float* out = (float*)d_out;

    convert_weights<<<2048, 256>>>(W_ih, W_hh);
    lstm_persistent<<<NBLK, NTHR>>>(idx, emb, b_ih, b_hh, out);
    (void)in_sizes; (void)n_in; (void)out_size;
}